// round 15
// baseline (speedup 1.0000x reference)
#include <cuda_runtime.h>
#include <cuda_fp16.h>
#include <math.h>
#include <stdint.h>

// Problem constants
#define BB   4
#define SS   128
#define TT   128
#define DD   256
#define NHEAD 8
#define HDIM  32
#define DFF  1024
#define NTOK (BB*SS*TT)          // 65536
#define EPSV 1.1920929e-07f
#define QK_SCALE_L2E (0.17677669529663687f * 1.44269504088896340f)

// ---------------- scratch ---------------------------------------------------
__device__ __half g_xh   [(size_t)NTOK * DD];
__device__ __half g_qkvh [(size_t)NTOK * 3 * DD];
__device__ __half g_attnh[(size_t)NTOK * DD];
__device__ __half g_hh   [(size_t)NTOK * DFF];
__device__ __half g_outh [(size_t)NTOK * DD];
__device__ __half g_wqs_h[3 * DD * DD];
__device__ __half g_wqt_h[3 * DD * DD];
__device__ __half g_wos_h[DD * DD];
__device__ __half g_wot_h[DD * DD];
__device__ __half g_w1_h [DFF * DD];
__device__ __half g_w2_h [DD * DFF];
__device__ float  g_ssq  [NTOK * 2];
__device__ uint32_t g_smaskbits[SS * 4];
__device__ uint32_t g_tmaskbits[TT * 4];

// ---------------- helpers ----------------------------------------------------
__device__ __forceinline__ uint32_t smem_u32(const void* p) {
    uint32_t a;
    asm("{ .reg .u64 t; cvta.to.shared.u64 t, %1; cvt.u32.u64 %0, t; }" : "=r"(a) : "l"(p));
    return a;
}
__device__ __forceinline__ void cp_async16(uint32_t dst, const void* src) {
    asm volatile("cp.async.cg.shared.global [%0], [%1], 16;" :: "r"(dst), "l"(src) : "memory");
}
__device__ __forceinline__ void cp_commit() {
    asm volatile("cp.async.commit_group;" ::: "memory");
}
template<int W> __device__ __forceinline__ void cp_wait() {
    asm volatile("cp.async.wait_group %0;" :: "n"(W) : "memory");
}
__device__ __forceinline__ void prefetch_l2(const void* p) {
    asm volatile("prefetch.global.L2 [%0];" :: "l"(p));
}
__device__ __forceinline__ void mma_f16(float* d, const uint32_t* a, const uint32_t* b) {
    asm volatile(
        "mma.sync.aligned.m16n8k16.row.col.f32.f16.f16.f32 "
        "{%0,%1,%2,%3}, {%4,%5,%6,%7}, {%8,%9}, {%0,%1,%2,%3};"
        : "+f"(d[0]), "+f"(d[1]), "+f"(d[2]), "+f"(d[3])
        : "r"(a[0]), "r"(a[1]), "r"(a[2]), "r"(a[3]), "r"(b[0]), "r"(b[1]));
}
__device__ __forceinline__ void ldsm_x4(uint32_t* r, uint32_t addr) {
    asm volatile("ldmatrix.sync.aligned.m8n8.x4.shared.b16 {%0,%1,%2,%3}, [%4];"
        : "=r"(r[0]), "=r"(r[1]), "=r"(r[2]), "=r"(r[3]) : "r"(addr));
}
__device__ __forceinline__ void ldsm_x4_t(uint32_t* r, uint32_t addr) {
    asm volatile("ldmatrix.sync.aligned.m8n8.x4.trans.shared.b16 {%0,%1,%2,%3}, [%4];"
        : "=r"(r[0]), "=r"(r[1]), "=r"(r[2]), "=r"(r[3]) : "r"(addr));
}
__device__ __forceinline__ uint32_t h2u(__half2 v) { return *(uint32_t*)&v; }
__device__ __forceinline__ uint32_t ex2_h2(uint32_t v) {
    uint32_t r;
    asm("ex2.approx.f16x2 %0, %1;" : "=r"(r) : "r"(v));
    return r;
}

// ---------------- fused prep: weights + masks (spatial+temporal) + rstd -------
#define PREP_BLKS  1028
#define RSTD_BLKS  (NTOK / 8)
__global__ void prep_k(const float* __restrict__ Wqkv_s, const float* __restrict__ g1,
                       const float* __restrict__ Wqkv_t, const float* __restrict__ g2,
                       const float* __restrict__ Wo_s, const float* __restrict__ Wo_t,
                       const float* __restrict__ W1, const float* __restrict__ g3,
                       const float* __restrict__ W2, const int* __restrict__ coords,
                       const float* __restrict__ x, __half* __restrict__ xh) {
    if (blockIdx.x >= PREP_BLKS) {
        int row  = (blockIdx.x - PREP_BLKS) * 8 + (threadIdx.x >> 5);
        int lane = threadIdx.x & 31;
        const float* xr = x + (size_t)row * DD + lane * 8;
        float4 a = *(const float4*)(xr);
        float4 b = *(const float4*)(xr + 4);
        float ss = a.x*a.x + a.y*a.y + a.z*a.z + a.w*a.w
                 + b.x*b.x + b.y*b.y + b.z*b.z + b.w*b.w;
        __half2 hh[4] = { __floats2half2_rn(a.x, a.y), __floats2half2_rn(a.z, a.w),
                          __floats2half2_rn(b.x, b.y), __floats2half2_rn(b.z, b.w) };
        *(uint4*)(xh + (size_t)row * DD + lane * 8) = *(uint4*)hh;
        #pragma unroll
        for (int m = 16; m > 0; m >>= 1) ss += __shfl_xor_sync(0xffffffffu, ss, m);
        if (lane == 0) { g_ssq[row * 2] = ss; g_ssq[row * 2 + 1] = 0.0f; }
        return;
    }
    int idx = blockIdx.x * 256 + threadIdx.x;
    if (idx < 262144) {
        const float* W; const float* g = nullptr; __half* out; int local;
        if (idx < 49152)       { W = Wqkv_s; g = g1; out = g_wqs_h; local = idx; }
        else if (idx < 98304)  { W = Wqkv_t; g = g2; out = g_wqt_h; local = idx - 49152; }
        else if (idx < 114688) { W = Wo_s;           out = g_wos_h; local = idx - 98304; }
        else if (idx < 131072) { W = Wo_t;           out = g_wot_h; local = idx - 114688; }
        else if (idx < 196608) { W = W1;     g = g3; out = g_w1_h;  local = idx - 131072; }
        else                   { W = W2;             out = g_w2_h;  local = idx - 196608; }
        float4 w = ((const float4*)W)[local];
        if (g) {
            float4 gv = ((const float4*)g)[local & (DD / 4 - 1)];
            w.x *= gv.x; w.y *= gv.y; w.z *= gv.z; w.w *= gv.w;
        }
        ((__half2*)out)[local * 2]     = __floats2half2_rn(w.x, w.y);
        ((__half2*)out)[local * 2 + 1] = __floats2half2_rn(w.z, w.w);
    } else if (idx < 262144 + 512) {
        int m = idx - 262144;
        int i = m >> 2, w = m & 3;
        uint32_t bits = 0;
        int xi = coords[2 * i], yi = coords[2 * i + 1];
        for (int k = 0; k < 32; k++) {
            int j = w * 32 + k;
            int dx = abs(xi - coords[2 * j]);
            int dy = abs(yi - coords[2 * j + 1]);
            if (max(dx, dy) <= 4) bits |= (1u << k);
        }
        g_smaskbits[m] = bits;
    } else if (idx < 262144 + 1024) {
        int m = idx - 262144 - 512;
        int i = m >> 2, w = m & 3;
        uint32_t bits = 0;
        for (int k = 0; k < 32; k++) {
            int j = w * 32 + k;
            int d = i - j;
            if (d >= 0 && d <= 3) bits |= (1u << k);
        }
        g_tmaskbits[m] = bits;
    }
}

// ---------------- fp16 mma GEMM (K compile-time) ------------------------------
#define HSTRIDE_B 144
#define ATILE_B   (128 * HSTRIDE_B)
#define STAGE_B   (2 * ATILE_B)
#define NSTAGE    3
#define GEMM_SMEM_BYTES (NSTAGE * STAGE_B)  // 110592

template<int EPI, bool NORM, bool WF32, bool WF16, bool SSQP, int KDIM>
__global__ void __launch_bounds__(256, 2) gemm_h_k(
    const __half* __restrict__ A, const __half* __restrict__ Bm,
    const float* __restrict__ bias, const float* __restrict__ res,
    float* __restrict__ Cf, __half* __restrict__ Ch, int M, int N)
{
    extern __shared__ char sm[];
    const int tid  = threadIdx.x;
    const int wid  = tid >> 5;
    const int lane = tid & 31;
    const int gid  = lane >> 2;
    const int tig  = lane & 3;
    const int warp_m = (wid & 1) * 64;
    const int warp_n = (wid >> 1) * 32;
    const int bm = blockIdx.y * 128;
    const int bn = blockIdx.x * 128;

    const uint32_t smbase = smem_u32(sm);

    uint32_t offA[4], offB[2];
    {
        const int aRow = lane & 15;
        const int aColB = (lane >> 4) * 16;
        #pragma unroll
        for (int mi = 0; mi < 4; mi++)
            offA[mi] = (uint32_t)(warp_m + mi * 16 + aRow) * HSTRIDE_B + aColB;
        const int bRow = (lane & 7) + (lane >> 4) * 8;
        const int bColB = (lane & 8) * 2;
        #pragma unroll
        for (int np = 0; np < 2; np++)
            offB[np] = (uint32_t)(warp_n + np * 16 + bRow) * HSTRIDE_B + bColB;
    }

    float acc[4][4][4];
    #pragma unroll
    for (int mi = 0; mi < 4; mi++)
        #pragma unroll
        for (int ni = 0; ni < 4; ni++)
            #pragma unroll
            for (int r = 0; r < 4; r++) acc[mi][ni][r] = 0.0f;

    constexpr int nCh = KDIM >> 6;
    const int ksRev = wid & 1;

    auto prefetch = [&](int ch, int s) {
        const int k0 = ch * 64;
        const uint32_t sa = smbase + (uint32_t)(s * STAGE_B);
        #pragma unroll
        for (int it = 0; it < 4; it++) {
            int f   = it * 256 + tid;
            int row = f >> 3;
            int c16 = f & 7;
            uint32_t off = (uint32_t)row * HSTRIDE_B + c16 * 16;
            cp_async16(sa + off,           A  + (size_t)(bm + row) * KDIM + k0 + c16 * 8);
            cp_async16(sa + off + ATILE_B, Bm + (size_t)(bn + row) * KDIM + k0 + c16 * 8);
        }
        cp_commit();
    };

    prefetch(0, 0);
    if (nCh > 1) prefetch(1, 1);

    // Warm the residual block into L2 while the mainloop runs (epilogue hides).
    if (EPI == 1) {
        #pragma unroll
        for (int p = 0; p < 2; p++) {
            int l = tid * 2 + p;                       // 512 lines of 128B
            prefetch_l2(res + (size_t)(bm + (l >> 2)) * N + bn + (l & 3) * 32);
        }
    }

    int stage = 0;
    #pragma unroll 4
    for (int ch = 0; ch < nCh; ch++) {
        cp_wait<1>();
        __syncthreads();

        if (ch + 2 < nCh) {
            int s2 = stage + 2; if (s2 >= NSTAGE) s2 -= NSTAGE;
            prefetch(ch + 2, s2);
        } else {
            cp_commit();
        }

        const uint32_t AsAddr = smbase + (uint32_t)(stage * STAGE_B);
        const uint32_t BsAddr = AsAddr + ATILE_B;

        #pragma unroll
        for (int ks = 0; ks < 4; ks++) {
            const int kss = ksRev ? (3 - ks) : ks;
            const uint32_t kb = (uint32_t)kss * 32;
            uint32_t a[4][4], b[2][4];
            #pragma unroll
            for (int mi = 0; mi < 4; mi++) ldsm_x4(a[mi], AsAddr + offA[mi] + kb);
            #pragma unroll
            for (int np = 0; np < 2; np++) ldsm_x4(b[np], BsAddr + offB[np] + kb);
            #pragma unroll
            for (int mi = 0; mi < 4; mi++)
                #pragma unroll
                for (int ni = 0; ni < 4; ni++)
                    mma_f16(acc[mi][ni], a[mi], &b[ni >> 1][(ni & 1) * 2]);
        }

        if (++stage == NSTAGE) stage = 0;
    }

    float* sred = (float*)sm;
    if (SSQP) __syncthreads();

    #pragma unroll
    for (int mi = 0; mi < 4; mi++) {
        #pragma unroll
        for (int h = 0; h < 2; h++) {
            const int rin = warp_m + mi * 16 + gid + h * 8;
            const int row = bm + rin;
            float rs = 1.0f;
            if (NORM) {
                float s2 = g_ssq[row * 2] + g_ssq[row * 2 + 1];
                rs = rsqrtf(s2 * (1.0f / DD) + EPSV);
            }
            float*  cf  = WF32 ? (Cf + (size_t)row * N) : (float*)nullptr;
            __half* chp = WF16 ? (Ch + (size_t)row * N) : (__half*)nullptr;
            const float* rp = (EPI == 1) ? (res + (size_t)row * N) : (const float*)nullptr;
            float sp = 0.0f;
            #pragma unroll
            for (int ni = 0; ni < 4; ni++) {
                const int col = bn + warp_n + ni * 8 + tig * 2;
                float v0 = acc[mi][ni][h * 2 + 0];
                float v1 = acc[mi][ni][h * 2 + 1];
                if (NORM) { v0 *= rs; v1 *= rs; }
                v0 += bias[col]; v1 += bias[col + 1];
                if (EPI == 1) {
                    float2 r = *(const float2*)(rp + col);
                    v0 += r.x; v1 += r.y;
                }
                if (EPI == 2) {
                    v0 = 0.5f * v0 * (1.0f + erff(v0 * 0.70710678118654752f));
                    v1 = 0.5f * v1 * (1.0f + erff(v1 * 0.70710678118654752f));
                }
                if (SSQP) sp += v0 * v0 + v1 * v1;
                if (WF32) *(float2*)(cf + col) = make_float2(v0, v1);
                if (WF16) *(__half2*)(chp + col) = __floats2half2_rn(v0, v1);
            }
            if (SSQP) {
                sp += __shfl_xor_sync(0xffffffffu, sp, 1);
                sp += __shfl_xor_sync(0xffffffffu, sp, 2);
                if (tig == 0) sred[rin * 4 + (wid >> 1)] = sp;
            }
        }
    }

    if (SSQP) {
        __syncthreads();
        if (tid < 128) {
            float s = sred[tid * 4] + sred[tid * 4 + 1] + sred[tid * 4 + 2] + sred[tid * 4 + 3];
            g_ssq[(bm + tid) * 2 + blockIdx.x] = s;
        }
    }
}

// ---------------- fp16 MMA flash attention: 2 heads per block -----------------
#define AKS_HSTR (128 * 40)
#define AVS_HSTR (128 * 56)
#define AVS_H    (2 * AKS_HSTR)
#define AMB_BYTE ((AVS_H + 2 * AVS_HSTR) * 2)   // 49152
#define ASMEM_BYTES (AMB_BYTE + 2048)           // 51200

template<bool TEMPORAL>
__global__ void __launch_bounds__(256, 2) attn_mma_k(const __half* __restrict__ qkv,
                                                     __half* __restrict__ out)
{
    extern __shared__ __half ash[];
    uint32_t* MB = (uint32_t*)((char*)ash + AMB_BYTE);

    const int sb  = blockIdx.x;
    const int hbase = blockIdx.y * 2;
    const int tid = threadIdx.x;
    const int w   = tid >> 5;
    const int hp  = w >> 2;
    const int wg  = w & 3;
    const int lane = tid & 31;
    const int gid  = lane >> 2;
    const int tig  = lane & 3;

    const uint32_t KsAddr = smem_u32(ash) + hp * (AKS_HSTR * 2);
    const uint32_t VsAddr = smem_u32(ash) + AVS_H * 2 + hp * (AVS_HSTR * 2);
    const uint32_t KsStage = smem_u32(ash);
    const uint32_t VsStage = smem_u32(ash) + AVS_H * 2;

    const int bhi = sb >> 7, blo = sb & 127;

    #pragma unroll
    for (int it = 0; it < 4; it++) {
        int s    = it * 256 + tid;
        int tok  = s >> 3;
        int c16  = s & 7;
        int head = c16 >> 2;
        int q4   = c16 & 3;
        int tok_g = TEMPORAL ? (bhi * (TT * SS) + tok * SS + blo) : (sb * 128 + tok);
        const __half* base = qkv + (size_t)tok_g * (3 * DD) + (hbase + head) * HDIM + q4 * 8;
        cp_async16(KsStage + head * (AKS_HSTR * 2) + tok * 80  + q4 * 16, base + DD);
        cp_async16(VsStage + head * (AVS_HSTR * 2) + tok * 112 + q4 * 16, base + 2 * DD);
    }
    cp_commit();

    {
        int head = tid >> 7, tok = tid & 127;
        __half* vp = ash + AVS_H + head * AVS_HSTR + tok * 56 + 32;
        uint4 z  = make_uint4(0, 0, 0, 0);
        uint4 o1 = make_uint4(0x00003C00u, 0, 0, 0);
        *(uint4*)(vp)      = o1;
        *(uint4*)(vp + 8)  = z;
        *(uint4*)(vp + 16) = z;
    }
    {
        const uint32_t* gmb = TEMPORAL ? g_tmaskbits : g_smaskbits;
        for (int i = tid; i < 512; i += 256) MB[i] = gmb[i];
    }

    const int h = hbase + hp;
    const int qbase = wg * 32;
    const __half2 qs2 = __float2half2_rn(QK_SCALE_L2E);

    uint32_t qa[2][2][4];
    #pragma unroll
    for (int mt = 0; mt < 2; mt++) {
        int rA = qbase + mt * 16 + gid;
        int tokA = TEMPORAL ? (bhi * (TT * SS) + rA * SS + blo) : (sb * 128 + rA);
        int tokB = TEMPORAL ? (bhi * (TT * SS) + (rA + 8) * SS + blo) : (sb * 128 + rA + 8);
        const __half* pA = qkv + (size_t)tokA * (3 * DD) + h * HDIM;
        const __half* pB = qkv + (size_t)tokB * (3 * DD) + h * HDIM;
        #pragma unroll
        for (int ks = 0; ks < 2; ks++) {
            qa[mt][ks][0] = h2u(__hmul2(*(const __half2*)(pA + ks * 16 + 2 * tig), qs2));
            qa[mt][ks][1] = h2u(__hmul2(*(const __half2*)(pB + ks * 16 + 2 * tig), qs2));
            qa[mt][ks][2] = h2u(__hmul2(*(const __half2*)(pA + ks * 16 + 2 * tig + 8), qs2));
            qa[mt][ks][3] = h2u(__hmul2(*(const __half2*)(pB + ks * 16 + 2 * tig + 8), qs2));
        }
    }

    cp_wait<0>();
    __syncthreads();

    const int bRow  = (lane & 7) + (lane >> 4) * 8;
    const int bColB = (lane & 8) * 2;
    const int vRow  = (lane & 7) + ((lane >> 3) & 1) * 8;
    const int vColH = ((lane >> 4) & 1) * 8;

    float o[2][4][4];
    float oS[2][4];
    #pragma unroll
    for (int mt = 0; mt < 2; mt++) {
        #pragma unroll
        for (int r = 0; r < 4; r++) oS[mt][r] = 0.0f;
        #pragma unroll
        for (int nt = 0; nt < 4; nt++)
            #pragma unroll
            for (int r = 0; r < 4; r++) o[mt][nt][r] = 0.0f;
    }

    const int jc_lo = TEMPORAL ? max(wg - 1, 0) : 0;
    const int jc_hi = TEMPORAL ? wg : 3;

    for (int jc = jc_lo; jc <= jc_hi; jc++) {
        float s[2][4][4];
        #pragma unroll
        for (int mt = 0; mt < 2; mt++)
            #pragma unroll
            for (int nt = 0; nt < 4; nt++)
                #pragma unroll
                for (int r = 0; r < 4; r++) s[mt][nt][r] = 0.0f;

        #pragma unroll
        for (int ks = 0; ks < 2; ks++) {
            uint32_t bk[2][4];
            #pragma unroll
            for (int np = 0; np < 2; np++) {
                uint32_t addr = KsAddr + (uint32_t)(jc * 32 + np * 16 + bRow) * 80
                              + bColB + ks * 32;
                ldsm_x4(bk[np], addr);
            }
            #pragma unroll
            for (int mt = 0; mt < 2; mt++)
                #pragma unroll
                for (int nt = 0; nt < 4; nt++)
                    mma_f16(s[mt][nt], qa[mt][ks], &bk[nt >> 1][(nt & 1) * 2]);
        }

        uint32_t ph[2][4][2];
        #pragma unroll
        for (int mt = 0; mt < 2; mt++) {
            int row0 = qbase + mt * 16 + gid;
            uint32_t mw0 = MB[row0 * 4 + jc];
            uint32_t mw1 = MB[(row0 + 8) * 4 + jc];
            #pragma unroll
            for (int nt = 0; nt < 4; nt++) {
                float sm0[2], sm1[2];
                #pragma unroll
                for (int c = 0; c < 2; c++) {
                    int kloc = nt * 8 + 2 * tig + c;
                    bool v0 = (mw0 >> kloc) & 1;
                    bool v1 = (mw1 >> kloc) & 1;
                    sm0[c] = v0 ? s[mt][nt][c]     : -50.0f;
                    sm1[c] = v1 ? s[mt][nt][c + 2] : -50.0f;
                }
                ph[mt][nt][0] = ex2_h2(h2u(__floats2half2_rn(sm0[0], sm0[1])));
                ph[mt][nt][1] = ex2_h2(h2u(__floats2half2_rn(sm1[0], sm1[1])));
            }
        }

        #pragma unroll
        for (int ks = 0; ks < 2; ks++) {
            uint32_t bv[3][4];
            #pragma unroll
            for (int np = 0; np < 3; np++) {
                uint32_t addr = VsAddr + (uint32_t)(jc * 32 + ks * 16 + vRow) * 112
                              + (np * 16 + vColH) * 2;
                ldsm_x4_t(bv[np], addr);
            }
            #pragma unroll
            for (int mt = 0; mt < 2; mt++) {
                uint32_t a[4] = { ph[mt][2 * ks][0],     ph[mt][2 * ks][1],
                                  ph[mt][2 * ks + 1][0], ph[mt][2 * ks + 1][1] };
                #pragma unroll
                for (int nt = 0; nt < 4; nt++)
                    mma_f16(o[mt][nt], a, &bv[nt >> 1][(nt & 1) * 2]);
                mma_f16(oS[mt], a, &bv[2][0]);
            }
        }
    }

    #pragma unroll
    for (int mt = 0; mt < 2; mt++) {
        #pragma unroll
        for (int h2 = 0; h2 < 2; h2++) {
            float l = __shfl_sync(0xffffffffu, oS[mt][h2 * 2], lane & ~3);
            float inv = 1.0f / l;
            int grow = qbase + mt * 16 + gid + h2 * 8;
            int tok  = TEMPORAL ? (bhi * (TT * SS) + grow * SS + blo) : (sb * 128 + grow);
            __half* op = out + (size_t)tok * DD + h * HDIM;
            #pragma unroll
            for (int nt = 0; nt < 4; nt++) {
                *(__half2*)(op + nt * 8 + 2 * tig) =
                    __floats2half2_rn(o[mt][nt][2 * h2] * inv, o[mt][nt][2 * h2 + 1] * inv);
            }
        }
    }
}

// ---------------- launch -----------------------------------------------------
extern "C" void kernel_launch(void* const* d_in, const int* in_sizes, int n_in,
                              void* d_out, int out_size) {
    const float* x      = (const float*)d_in[0];
    const int*   coords = (const int*)  d_in[1];
    const float* Wqkv_s = (const float*)d_in[3];
    const float* bqkv_s = (const float*)d_in[4];
    const float* Wo_s   = (const float*)d_in[5];
    const float* bo_s   = (const float*)d_in[6];
    const float* Wqkv_t = (const float*)d_in[7];
    const float* bqkv_t = (const float*)d_in[8];
    const float* Wo_t   = (const float*)d_in[9];
    const float* bo_t   = (const float*)d_in[10];
    const float* g1     = (const float*)d_in[11];
    const float* g2     = (const float*)d_in[12];
    const float* g3     = (const float*)d_in[13];
    const float* W1     = (const float*)d_in[14];
    const float* b1     = (const float*)d_in[15];
    const float* W2     = (const float*)d_in[16];
    const float* b2     = (const float*)d_in[17];
    float* out = (float*)d_out;

    __half *xh, *qkvh, *attnh, *hh, *outh, *wqs, *wqt, *wos, *wot, *w1h, *w2h;
    cudaGetSymbolAddress((void**)&xh,    g_xh);
    cudaGetSymbolAddress((void**)&qkvh,  g_qkvh);
    cudaGetSymbolAddress((void**)&attnh, g_attnh);
    cudaGetSymbolAddress((void**)&hh,    g_hh);
    cudaGetSymbolAddress((void**)&outh,  g_outh);
    cudaGetSymbolAddress((void**)&wqs,   g_wqs_h);
    cudaGetSymbolAddress((void**)&wqt,   g_wqt_h);
    cudaGetSymbolAddress((void**)&wos,   g_wos_h);
    cudaGetSymbolAddress((void**)&wot,   g_wot_h);
    cudaGetSymbolAddress((void**)&w1h,   g_w1_h);
    cudaGetSymbolAddress((void**)&w2h,   g_w2_h);

    static bool attr_set = false;
    if (!attr_set) {
        cudaFuncSetAttribute(gemm_h_k<0,true,false,true,false,256>, cudaFuncAttributeMaxDynamicSharedMemorySize, GEMM_SMEM_BYTES);
        cudaFuncSetAttribute(gemm_h_k<1,false,true,true,true,256>,  cudaFuncAttributeMaxDynamicSharedMemorySize, GEMM_SMEM_BYTES);
        cudaFuncSetAttribute(gemm_h_k<2,true,false,true,false,256>, cudaFuncAttributeMaxDynamicSharedMemorySize, GEMM_SMEM_BYTES);
        cudaFuncSetAttribute(gemm_h_k<1,false,true,false,false,1024>,cudaFuncAttributeMaxDynamicSharedMemorySize, GEMM_SMEM_BYTES);
        cudaFuncSetAttribute(attn_mma_k<false>, cudaFuncAttributeMaxDynamicSharedMemorySize, ASMEM_BYTES);
        cudaFuncSetAttribute(attn_mma_k<true>,  cudaFuncAttributeMaxDynamicSharedMemorySize, ASMEM_BYTES);
        attr_set = true;
    }

    const dim3 tb256(256);
    const dim3 gQKV(3 * DD / 128, NTOK / 128);   // (6, 512)
    const dim3 gO  (DD / 128,     NTOK / 128);   // (2, 512)
    const dim3 gF1 (DFF / 128,    NTOK / 128);   // (8, 512)
    const dim3 gAttn(BB * TT, NHEAD / 2);        // (512, 4)

    prep_k<<<PREP_BLKS + RSTD_BLKS, tb256>>>(Wqkv_s, g1, Wqkv_t, g2, Wo_s, Wo_t, W1, g3, W2,
                                             coords, x, xh);

    // --- spatial block ---
    gemm_h_k<0,true,false,true,false,256><<<gQKV, tb256, GEMM_SMEM_BYTES>>>(
        xh, wqs, bqkv_s, nullptr, nullptr, qkvh, NTOK, 3 * DD);
    attn_mma_k<false><<<gAttn, tb256, ASMEM_BYTES>>>(qkvh, attnh);
    gemm_h_k<1,false,true,true,true,256><<<gO, tb256, GEMM_SMEM_BYTES>>>(
        attnh, wos, bo_s, x, out, outh, NTOK, DD);

    // --- temporal block ---
    gemm_h_k<0,true,false,true,false,256><<<gQKV, tb256, GEMM_SMEM_BYTES>>>(
        outh, wqt, bqkv_t, nullptr, nullptr, qkvh, NTOK, 3 * DD);
    attn_mma_k<true><<<gAttn, tb256, ASMEM_BYTES>>>(qkvh, attnh);
    gemm_h_k<1,false,true,true,true,256><<<gO, tb256, GEMM_SMEM_BYTES>>>(
        attnh, wot, bo_t, out, out, outh, NTOK, DD);

    // --- FFN ---
    gemm_h_k<2,true,false,true,false,256><<<gF1, tb256, GEMM_SMEM_BYTES>>>(
        outh, w1h, b1, nullptr, nullptr, hh, NTOK, DFF);
    gemm_h_k<1,false,true,false,false,1024><<<gO, tb256, GEMM_SMEM_BYTES>>>(
        hh, w2h, b2, out, out, nullptr, NTOK, DD);
}

// round 16
// speedup vs baseline: 1.0659x; 1.0659x over previous
#include <cuda_runtime.h>
#include <cuda_fp16.h>
#include <math.h>
#include <stdint.h>

// Problem constants
#define BB   4
#define SS   128
#define TT   128
#define DD   256
#define NHEAD 8
#define HDIM  32
#define DFF  1024
#define NTOK (BB*SS*TT)          // 65536
#define EPSV 1.1920929e-07f
#define QK_SCALE_L2E (0.17677669529663687f * 1.44269504088896340f)

// ---------------- scratch ---------------------------------------------------
__device__ __half g_xh   [(size_t)NTOK * DD];
__device__ __half g_qkvh [(size_t)NTOK * 3 * DD];
__device__ __half g_attnh[(size_t)NTOK * DD];
__device__ __half g_hh   [(size_t)NTOK * DFF];
__device__ __half g_outh [(size_t)NTOK * DD];
__device__ __half g_wqs_h[3 * DD * DD];
__device__ __half g_wqt_h[3 * DD * DD];
__device__ __half g_wos_h[DD * DD];
__device__ __half g_wot_h[DD * DD];
__device__ __half g_w1_h [DFF * DD];
__device__ __half g_w2_h [DD * DFF];
__device__ float  g_ssq  [NTOK * 2];
__device__ uint32_t g_smaskbits[SS * 4];
__device__ uint32_t g_tmaskbits[TT * 4];

// ---------------- helpers ----------------------------------------------------
__device__ __forceinline__ uint32_t smem_u32(const void* p) {
    uint32_t a;
    asm("{ .reg .u64 t; cvta.to.shared.u64 t, %1; cvt.u32.u64 %0, t; }" : "=r"(a) : "l"(p));
    return a;
}
__device__ __forceinline__ void cp_async16(uint32_t dst, const void* src) {
    asm volatile("cp.async.cg.shared.global [%0], [%1], 16;" :: "r"(dst), "l"(src) : "memory");
}
__device__ __forceinline__ void cp_commit() {
    asm volatile("cp.async.commit_group;" ::: "memory");
}
template<int W> __device__ __forceinline__ void cp_wait() {
    asm volatile("cp.async.wait_group %0;" :: "n"(W) : "memory");
}
__device__ __forceinline__ void mma_f16(float* d, const uint32_t* a, const uint32_t* b) {
    asm volatile(
        "mma.sync.aligned.m16n8k16.row.col.f32.f16.f16.f32 "
        "{%0,%1,%2,%3}, {%4,%5,%6,%7}, {%8,%9}, {%0,%1,%2,%3};"
        : "+f"(d[0]), "+f"(d[1]), "+f"(d[2]), "+f"(d[3])
        : "r"(a[0]), "r"(a[1]), "r"(a[2]), "r"(a[3]), "r"(b[0]), "r"(b[1]));
}
__device__ __forceinline__ void ldsm_x4(uint32_t* r, uint32_t addr) {
    asm volatile("ldmatrix.sync.aligned.m8n8.x4.shared.b16 {%0,%1,%2,%3}, [%4];"
        : "=r"(r[0]), "=r"(r[1]), "=r"(r[2]), "=r"(r[3]) : "r"(addr));
}
__device__ __forceinline__ void ldsm_x4_t(uint32_t* r, uint32_t addr) {
    asm volatile("ldmatrix.sync.aligned.m8n8.x4.trans.shared.b16 {%0,%1,%2,%3}, [%4];"
        : "=r"(r[0]), "=r"(r[1]), "=r"(r[2]), "=r"(r[3]) : "r"(addr));
}
__device__ __forceinline__ uint32_t h2u(__half2 v) { return *(uint32_t*)&v; }
__device__ __forceinline__ uint32_t ex2_h2(uint32_t v) {
    uint32_t r;
    asm("ex2.approx.f16x2 %0, %1;" : "=r"(r) : "r"(v));
    return r;
}

// ---------------- fused prep: weights + masks (spatial+temporal) + rstd -------
#define PREP_BLKS  1028
#define RSTD_BLKS  (NTOK / 8)
__global__ void prep_k(const float* __restrict__ Wqkv_s, const float* __restrict__ g1,
                       const float* __restrict__ Wqkv_t, const float* __restrict__ g2,
                       const float* __restrict__ Wo_s, const float* __restrict__ Wo_t,
                       const float* __restrict__ W1, const float* __restrict__ g3,
                       const float* __restrict__ W2, const int* __restrict__ coords,
                       const float* __restrict__ x, __half* __restrict__ xh) {
    if (blockIdx.x >= PREP_BLKS) {
        int row  = (blockIdx.x - PREP_BLKS) * 8 + (threadIdx.x >> 5);
        int lane = threadIdx.x & 31;
        const float* xr = x + (size_t)row * DD + lane * 8;
        float4 a = *(const float4*)(xr);
        float4 b = *(const float4*)(xr + 4);
        float ss = a.x*a.x + a.y*a.y + a.z*a.z + a.w*a.w
                 + b.x*b.x + b.y*b.y + b.z*b.z + b.w*b.w;
        __half2 hh[4] = { __floats2half2_rn(a.x, a.y), __floats2half2_rn(a.z, a.w),
                          __floats2half2_rn(b.x, b.y), __floats2half2_rn(b.z, b.w) };
        *(uint4*)(xh + (size_t)row * DD + lane * 8) = *(uint4*)hh;
        #pragma unroll
        for (int m = 16; m > 0; m >>= 1) ss += __shfl_xor_sync(0xffffffffu, ss, m);
        if (lane == 0) { g_ssq[row * 2] = ss; g_ssq[row * 2 + 1] = 0.0f; }
        return;
    }
    int idx = blockIdx.x * 256 + threadIdx.x;
    if (idx < 262144) {
        const float* W; const float* g = nullptr; __half* out; int local;
        if (idx < 49152)       { W = Wqkv_s; g = g1; out = g_wqs_h; local = idx; }
        else if (idx < 98304)  { W = Wqkv_t; g = g2; out = g_wqt_h; local = idx - 49152; }
        else if (idx < 114688) { W = Wo_s;           out = g_wos_h; local = idx - 98304; }
        else if (idx < 131072) { W = Wo_t;           out = g_wot_h; local = idx - 114688; }
        else if (idx < 196608) { W = W1;     g = g3; out = g_w1_h;  local = idx - 131072; }
        else                   { W = W2;             out = g_w2_h;  local = idx - 196608; }
        float4 w = ((const float4*)W)[local];
        if (g) {
            float4 gv = ((const float4*)g)[local & (DD / 4 - 1)];
            w.x *= gv.x; w.y *= gv.y; w.z *= gv.z; w.w *= gv.w;
        }
        ((__half2*)out)[local * 2]     = __floats2half2_rn(w.x, w.y);
        ((__half2*)out)[local * 2 + 1] = __floats2half2_rn(w.z, w.w);
    } else if (idx < 262144 + 512) {
        int m = idx - 262144;
        int i = m >> 2, w = m & 3;
        uint32_t bits = 0;
        int xi = coords[2 * i], yi = coords[2 * i + 1];
        for (int k = 0; k < 32; k++) {
            int j = w * 32 + k;
            int dx = abs(xi - coords[2 * j]);
            int dy = abs(yi - coords[2 * j + 1]);
            if (max(dx, dy) <= 4) bits |= (1u << k);
        }
        g_smaskbits[m] = bits;
    } else if (idx < 262144 + 1024) {
        int m = idx - 262144 - 512;
        int i = m >> 2, w = m & 3;
        uint32_t bits = 0;
        for (int k = 0; k < 32; k++) {
            int j = w * 32 + k;
            int d = i - j;
            if (d >= 0 && d <= 3) bits |= (1u << k);
        }
        g_tmaskbits[m] = bits;
    }
}

// ---------------- fp16 mma GEMM (K compile-time) ------------------------------
#define HSTRIDE_B 144
#define ATILE_B   (128 * HSTRIDE_B)
#define STAGE_B   (2 * ATILE_B)
#define NSTAGE    3
#define GEMM_SMEM_BYTES (NSTAGE * STAGE_B)  // 110592

template<int EPI, bool NORM, bool WF32, bool WF16, bool SSQP, int KDIM>
__global__ void __launch_bounds__(256, 2) gemm_h_k(
    const __half* __restrict__ A, const __half* __restrict__ Bm,
    const float* __restrict__ bias, const float* __restrict__ res,
    float* __restrict__ Cf, __half* __restrict__ Ch, int M, int N)
{
    extern __shared__ char sm[];
    const int tid  = threadIdx.x;
    const int wid  = tid >> 5;
    const int lane = tid & 31;
    const int gid  = lane >> 2;
    const int tig  = lane & 3;
    const int warp_m = (wid & 1) * 64;
    const int warp_n = (wid >> 1) * 32;
    const int bm = blockIdx.y * 128;
    const int bn = blockIdx.x * 128;

    const uint32_t smbase = smem_u32(sm);

    uint32_t offA[4], offB[2];
    {
        const int aRow = lane & 15;
        const int aColB = (lane >> 4) * 16;
        #pragma unroll
        for (int mi = 0; mi < 4; mi++)
            offA[mi] = (uint32_t)(warp_m + mi * 16 + aRow) * HSTRIDE_B + aColB;
        const int bRow = (lane & 7) + (lane >> 4) * 8;
        const int bColB = (lane & 8) * 2;
        #pragma unroll
        for (int np = 0; np < 2; np++)
            offB[np] = (uint32_t)(warp_n + np * 16 + bRow) * HSTRIDE_B + bColB;
    }

    float acc[4][4][4];
    #pragma unroll
    for (int mi = 0; mi < 4; mi++)
        #pragma unroll
        for (int ni = 0; ni < 4; ni++)
            #pragma unroll
            for (int r = 0; r < 4; r++) acc[mi][ni][r] = 0.0f;

    constexpr int nCh = KDIM >> 6;
    const int ksRev = wid & 1;

    auto prefetch = [&](int ch, int s) {
        const int k0 = ch * 64;
        const uint32_t sa = smbase + (uint32_t)(s * STAGE_B);
        #pragma unroll
        for (int it = 0; it < 4; it++) {
            int f   = it * 256 + tid;
            int row = f >> 3;
            int c16 = f & 7;
            uint32_t off = (uint32_t)row * HSTRIDE_B + c16 * 16;
            cp_async16(sa + off,           A  + (size_t)(bm + row) * KDIM + k0 + c16 * 8);
            cp_async16(sa + off + ATILE_B, Bm + (size_t)(bn + row) * KDIM + k0 + c16 * 8);
        }
        cp_commit();
    };

    prefetch(0, 0);
    if (nCh > 1) prefetch(1, 1);

    int stage = 0;
    #pragma unroll 4
    for (int ch = 0; ch < nCh; ch++) {
        cp_wait<1>();
        __syncthreads();

        if (ch + 2 < nCh) {
            int s2 = stage + 2; if (s2 >= NSTAGE) s2 -= NSTAGE;
            prefetch(ch + 2, s2);
        } else {
            cp_commit();
        }

        const uint32_t AsAddr = smbase + (uint32_t)(stage * STAGE_B);
        const uint32_t BsAddr = AsAddr + ATILE_B;

        #pragma unroll
        for (int ks = 0; ks < 4; ks++) {
            const int kss = ksRev ? (3 - ks) : ks;
            const uint32_t kb = (uint32_t)kss * 32;
            uint32_t a[4][4], b[2][4];
            #pragma unroll
            for (int mi = 0; mi < 4; mi++) ldsm_x4(a[mi], AsAddr + offA[mi] + kb);
            #pragma unroll
            for (int np = 0; np < 2; np++) ldsm_x4(b[np], BsAddr + offB[np] + kb);
            #pragma unroll
            for (int mi = 0; mi < 4; mi++)
                #pragma unroll
                for (int ni = 0; ni < 4; ni++)
                    mma_f16(acc[mi][ni], a[mi], &b[ni >> 1][(ni & 1) * 2]);
        }

        if (++stage == NSTAGE) stage = 0;
    }

    float* sred = (float*)sm;
    if (SSQP) __syncthreads();

    #pragma unroll
    for (int mi = 0; mi < 4; mi++) {
        #pragma unroll
        for (int h = 0; h < 2; h++) {
            const int rin = warp_m + mi * 16 + gid + h * 8;
            const int row = bm + rin;
            float rs = 1.0f;
            if (NORM) {
                float s2 = g_ssq[row * 2] + g_ssq[row * 2 + 1];
                rs = rsqrtf(s2 * (1.0f / DD) + EPSV);
            }
            float*  cf  = WF32 ? (Cf + (size_t)row * N) : (float*)nullptr;
            __half* chp = WF16 ? (Ch + (size_t)row * N) : (__half*)nullptr;
            const float* rp = (EPI == 1) ? (res + (size_t)row * N) : (const float*)nullptr;
            float sp = 0.0f;
            #pragma unroll
            for (int ni = 0; ni < 4; ni++) {
                const int col = bn + warp_n + ni * 8 + tig * 2;
                float v0 = acc[mi][ni][h * 2 + 0];
                float v1 = acc[mi][ni][h * 2 + 1];
                if (NORM) { v0 *= rs; v1 *= rs; }
                v0 += bias[col]; v1 += bias[col + 1];
                if (EPI == 1) {
                    float2 r = *(const float2*)(rp + col);
                    v0 += r.x; v1 += r.y;
                }
                if (EPI == 2) {
                    v0 = 0.5f * v0 * (1.0f + erff(v0 * 0.70710678118654752f));
                    v1 = 0.5f * v1 * (1.0f + erff(v1 * 0.70710678118654752f));
                }
                if (SSQP) sp += v0 * v0 + v1 * v1;
                if (WF32) *(float2*)(cf + col) = make_float2(v0, v1);
                if (WF16) *(__half2*)(chp + col) = __floats2half2_rn(v0, v1);
            }
            if (SSQP) {
                sp += __shfl_xor_sync(0xffffffffu, sp, 1);
                sp += __shfl_xor_sync(0xffffffffu, sp, 2);
                if (tig == 0) sred[rin * 4 + (wid >> 1)] = sp;
            }
        }
    }

    if (SSQP) {
        __syncthreads();
        if (tid < 128) {
            float s = sred[tid * 4] + sred[tid * 4 + 1] + sred[tid * 4 + 2] + sred[tid * 4 + 3];
            g_ssq[(bm + tid) * 2 + blockIdx.x] = s;
        }
    }
}

// ---------------- fp16 MMA flash attention: 2 heads per block -----------------
#define AKS_HSTR (128 * 40)
#define AVS_HSTR (128 * 56)
#define AVS_H    (2 * AKS_HSTR)
#define AMB_BYTE ((AVS_H + 2 * AVS_HSTR) * 2)   // 49152
#define ASMEM_BYTES (AMB_BYTE + 2048)           // 51200

template<bool TEMPORAL>
__global__ void __launch_bounds__(256, 2) attn_mma_k(const __half* __restrict__ qkv,
                                                     __half* __restrict__ out)
{
    extern __shared__ __half ash[];
    uint32_t* MB = (uint32_t*)((char*)ash + AMB_BYTE);

    const int sb  = blockIdx.x;
    const int hbase = blockIdx.y * 2;
    const int tid = threadIdx.x;
    const int w   = tid >> 5;
    const int hp  = w >> 2;
    const int wg  = w & 3;
    const int lane = tid & 31;
    const int gid  = lane >> 2;
    const int tig  = lane & 3;

    const uint32_t KsAddr = smem_u32(ash) + hp * (AKS_HSTR * 2);
    const uint32_t VsAddr = smem_u32(ash) + AVS_H * 2 + hp * (AVS_HSTR * 2);
    const uint32_t KsStage = smem_u32(ash);
    const uint32_t VsStage = smem_u32(ash) + AVS_H * 2;

    const int bhi = sb >> 7, blo = sb & 127;

    #pragma unroll
    for (int it = 0; it < 4; it++) {
        int s    = it * 256 + tid;
        int tok  = s >> 3;
        int c16  = s & 7;
        int head = c16 >> 2;
        int q4   = c16 & 3;
        int tok_g = TEMPORAL ? (bhi * (TT * SS) + tok * SS + blo) : (sb * 128 + tok);
        const __half* base = qkv + (size_t)tok_g * (3 * DD) + (hbase + head) * HDIM + q4 * 8;
        cp_async16(KsStage + head * (AKS_HSTR * 2) + tok * 80  + q4 * 16, base + DD);
        cp_async16(VsStage + head * (AVS_HSTR * 2) + tok * 112 + q4 * 16, base + 2 * DD);
    }
    cp_commit();

    {
        int head = tid >> 7, tok = tid & 127;
        __half* vp = ash + AVS_H + head * AVS_HSTR + tok * 56 + 32;
        uint4 z  = make_uint4(0, 0, 0, 0);
        uint4 o1 = make_uint4(0x00003C00u, 0, 0, 0);
        *(uint4*)(vp)      = o1;
        *(uint4*)(vp + 8)  = z;
        *(uint4*)(vp + 16) = z;
    }
    {
        const uint32_t* gmb = TEMPORAL ? g_tmaskbits : g_smaskbits;
        for (int i = tid; i < 512; i += 256) MB[i] = gmb[i];
    }

    const int h = hbase + hp;
    const int qbase = wg * 32;
    const __half2 qs2 = __float2half2_rn(QK_SCALE_L2E);

    uint32_t qa[2][2][4];
    #pragma unroll
    for (int mt = 0; mt < 2; mt++) {
        int rA = qbase + mt * 16 + gid;
        int tokA = TEMPORAL ? (bhi * (TT * SS) + rA * SS + blo) : (sb * 128 + rA);
        int tokB = TEMPORAL ? (bhi * (TT * SS) + (rA + 8) * SS + blo) : (sb * 128 + rA + 8);
        const __half* pA = qkv + (size_t)tokA * (3 * DD) + h * HDIM;
        const __half* pB = qkv + (size_t)tokB * (3 * DD) + h * HDIM;
        #pragma unroll
        for (int ks = 0; ks < 2; ks++) {
            qa[mt][ks][0] = h2u(__hmul2(*(const __half2*)(pA + ks * 16 + 2 * tig), qs2));
            qa[mt][ks][1] = h2u(__hmul2(*(const __half2*)(pB + ks * 16 + 2 * tig), qs2));
            qa[mt][ks][2] = h2u(__hmul2(*(const __half2*)(pA + ks * 16 + 2 * tig + 8), qs2));
            qa[mt][ks][3] = h2u(__hmul2(*(const __half2*)(pB + ks * 16 + 2 * tig + 8), qs2));
        }
    }

    cp_wait<0>();
    __syncthreads();

    const int bRow  = (lane & 7) + (lane >> 4) * 8;
    const int bColB = (lane & 8) * 2;
    const int vRow  = (lane & 7) + ((lane >> 3) & 1) * 8;
    const int vColH = ((lane >> 4) & 1) * 8;

    float o[2][4][4];
    float oS[2][4];
    #pragma unroll
    for (int mt = 0; mt < 2; mt++) {
        #pragma unroll
        for (int r = 0; r < 4; r++) oS[mt][r] = 0.0f;
        #pragma unroll
        for (int nt = 0; nt < 4; nt++)
            #pragma unroll
            for (int r = 0; r < 4; r++) o[mt][nt][r] = 0.0f;
    }

    const int jc_lo = TEMPORAL ? max(wg - 1, 0) : 0;
    const int jc_hi = TEMPORAL ? wg : 3;

    for (int jc = jc_lo; jc <= jc_hi; jc++) {
        float s[2][4][4];
        #pragma unroll
        for (int mt = 0; mt < 2; mt++)
            #pragma unroll
            for (int nt = 0; nt < 4; nt++)
                #pragma unroll
                for (int r = 0; r < 4; r++) s[mt][nt][r] = 0.0f;

        #pragma unroll
        for (int ks = 0; ks < 2; ks++) {
            uint32_t bk[2][4];
            #pragma unroll
            for (int np = 0; np < 2; np++) {
                uint32_t addr = KsAddr + (uint32_t)(jc * 32 + np * 16 + bRow) * 80
                              + bColB + ks * 32;
                ldsm_x4(bk[np], addr);
            }
            #pragma unroll
            for (int mt = 0; mt < 2; mt++)
                #pragma unroll
                for (int nt = 0; nt < 4; nt++)
                    mma_f16(s[mt][nt], qa[mt][ks], &bk[nt >> 1][(nt & 1) * 2]);
        }

        uint32_t ph[2][4][2];
        #pragma unroll
        for (int mt = 0; mt < 2; mt++) {
            int row0 = qbase + mt * 16 + gid;
            uint32_t mw0 = MB[row0 * 4 + jc];
            uint32_t mw1 = MB[(row0 + 8) * 4 + jc];
            #pragma unroll
            for (int nt = 0; nt < 4; nt++) {
                float sm0[2], sm1[2];
                #pragma unroll
                for (int c = 0; c < 2; c++) {
                    int kloc = nt * 8 + 2 * tig + c;
                    bool v0 = (mw0 >> kloc) & 1;
                    bool v1 = (mw1 >> kloc) & 1;
                    sm0[c] = v0 ? s[mt][nt][c]     : -50.0f;
                    sm1[c] = v1 ? s[mt][nt][c + 2] : -50.0f;
                }
                ph[mt][nt][0] = ex2_h2(h2u(__floats2half2_rn(sm0[0], sm0[1])));
                ph[mt][nt][1] = ex2_h2(h2u(__floats2half2_rn(sm1[0], sm1[1])));
            }
        }

        #pragma unroll
        for (int ks = 0; ks < 2; ks++) {
            uint32_t bv[3][4];
            #pragma unroll
            for (int np = 0; np < 3; np++) {
                uint32_t addr = VsAddr + (uint32_t)(jc * 32 + ks * 16 + vRow) * 112
                              + (np * 16 + vColH) * 2;
                ldsm_x4_t(bv[np], addr);
            }
            #pragma unroll
            for (int mt = 0; mt < 2; mt++) {
                uint32_t a[4] = { ph[mt][2 * ks][0],     ph[mt][2 * ks][1],
                                  ph[mt][2 * ks + 1][0], ph[mt][2 * ks + 1][1] };
                #pragma unroll
                for (int nt = 0; nt < 4; nt++)
                    mma_f16(o[mt][nt], a, &bv[nt >> 1][(nt & 1) * 2]);
                mma_f16(oS[mt], a, &bv[2][0]);
            }
        }
    }

    #pragma unroll
    for (int mt = 0; mt < 2; mt++) {
        #pragma unroll
        for (int h2 = 0; h2 < 2; h2++) {
            float l = __shfl_sync(0xffffffffu, oS[mt][h2 * 2], lane & ~3);
            float inv = 1.0f / l;
            int grow = qbase + mt * 16 + gid + h2 * 8;
            int tok  = TEMPORAL ? (bhi * (TT * SS) + grow * SS + blo) : (sb * 128 + grow);
            __half* op = out + (size_t)tok * DD + h * HDIM;
            #pragma unroll
            for (int nt = 0; nt < 4; nt++) {
                *(__half2*)(op + nt * 8 + 2 * tig) =
                    __floats2half2_rn(o[mt][nt][2 * h2] * inv, o[mt][nt][2 * h2 + 1] * inv);
            }
        }
    }
}

// ---------------- launch -----------------------------------------------------
extern "C" void kernel_launch(void* const* d_in, const int* in_sizes, int n_in,
                              void* d_out, int out_size) {
    const float* x      = (const float*)d_in[0];
    const int*   coords = (const int*)  d_in[1];
    const float* Wqkv_s = (const float*)d_in[3];
    const float* bqkv_s = (const float*)d_in[4];
    const float* Wo_s   = (const float*)d_in[5];
    const float* bo_s   = (const float*)d_in[6];
    const float* Wqkv_t = (const float*)d_in[7];
    const float* bqkv_t = (const float*)d_in[8];
    const float* Wo_t   = (const float*)d_in[9];
    const float* bo_t   = (const float*)d_in[10];
    const float* g1     = (const float*)d_in[11];
    const float* g2     = (const float*)d_in[12];
    const float* g3     = (const float*)d_in[13];
    const float* W1     = (const float*)d_in[14];
    const float* b1     = (const float*)d_in[15];
    const float* W2     = (const float*)d_in[16];
    const float* b2     = (const float*)d_in[17];
    float* out = (float*)d_out;

    __half *xh, *qkvh, *attnh, *hh, *outh, *wqs, *wqt, *wos, *wot, *w1h, *w2h;
    cudaGetSymbolAddress((void**)&xh,    g_xh);
    cudaGetSymbolAddress((void**)&qkvh,  g_qkvh);
    cudaGetSymbolAddress((void**)&attnh, g_attnh);
    cudaGetSymbolAddress((void**)&hh,    g_hh);
    cudaGetSymbolAddress((void**)&outh,  g_outh);
    cudaGetSymbolAddress((void**)&wqs,   g_wqs_h);
    cudaGetSymbolAddress((void**)&wqt,   g_wqt_h);
    cudaGetSymbolAddress((void**)&wos,   g_wos_h);
    cudaGetSymbolAddress((void**)&wot,   g_wot_h);
    cudaGetSymbolAddress((void**)&w1h,   g_w1_h);
    cudaGetSymbolAddress((void**)&w2h,   g_w2_h);

    static bool attr_set = false;
    if (!attr_set) {
        cudaFuncSetAttribute(gemm_h_k<0,true,false,true,false,256>, cudaFuncAttributeMaxDynamicSharedMemorySize, GEMM_SMEM_BYTES);
        cudaFuncSetAttribute(gemm_h_k<1,false,true,true,true,256>,  cudaFuncAttributeMaxDynamicSharedMemorySize, GEMM_SMEM_BYTES);
        cudaFuncSetAttribute(gemm_h_k<2,true,false,true,false,256>, cudaFuncAttributeMaxDynamicSharedMemorySize, GEMM_SMEM_BYTES);
        cudaFuncSetAttribute(gemm_h_k<1,false,true,false,false,1024>,cudaFuncAttributeMaxDynamicSharedMemorySize, GEMM_SMEM_BYTES);
        cudaFuncSetAttribute(attn_mma_k<false>, cudaFuncAttributeMaxDynamicSharedMemorySize, ASMEM_BYTES);
        cudaFuncSetAttribute(attn_mma_k<true>,  cudaFuncAttributeMaxDynamicSharedMemorySize, ASMEM_BYTES);
        attr_set = true;
    }

    const dim3 tb256(256);
    const dim3 gQKV(3 * DD / 128, NTOK / 128);   // (6, 512)
    const dim3 gO  (DD / 128,     NTOK / 128);   // (2, 512)
    const dim3 gF1 (DFF / 128,    NTOK / 128);   // (8, 512)
    const dim3 gAttn(BB * TT, NHEAD / 2);        // (512, 4)

    prep_k<<<PREP_BLKS + RSTD_BLKS, tb256>>>(Wqkv_s, g1, Wqkv_t, g2, Wo_s, Wo_t, W1, g3, W2,
                                             coords, x, xh);

    // --- spatial block ---
    gemm_h_k<0,true,false,true,false,256><<<gQKV, tb256, GEMM_SMEM_BYTES>>>(
        xh, wqs, bqkv_s, nullptr, nullptr, qkvh, NTOK, 3 * DD);
    attn_mma_k<false><<<gAttn, tb256, ASMEM_BYTES>>>(qkvh, attnh);
    gemm_h_k<1,false,true,true,true,256><<<gO, tb256, GEMM_SMEM_BYTES>>>(
        attnh, wos, bo_s, x, out, outh, NTOK, DD);

    // --- temporal block ---
    gemm_h_k<0,true,false,true,false,256><<<gQKV, tb256, GEMM_SMEM_BYTES>>>(
        outh, wqt, bqkv_t, nullptr, nullptr, qkvh, NTOK, 3 * DD);
    attn_mma_k<true><<<gAttn, tb256, ASMEM_BYTES>>>(qkvh, attnh);
    gemm_h_k<1,false,true,true,true,256><<<gO, tb256, GEMM_SMEM_BYTES>>>(
        attnh, wot, bo_t, out, out, outh, NTOK, DD);

    // --- FFN ---
    gemm_h_k<2,true,false,true,false,256><<<gF1, tb256, GEMM_SMEM_BYTES>>>(
        outh, w1h, b1, nullptr, nullptr, hh, NTOK, DFF);
    gemm_h_k<1,false,true,false,false,1024><<<gO, tb256, GEMM_SMEM_BYTES>>>(
        hh, w2h, b2, out, out, nullptr, NTOK, DD);
}

// round 17
// speedup vs baseline: 1.0930x; 1.0254x over previous
#include <cuda_runtime.h>
#include <cuda_fp16.h>
#include <math.h>
#include <stdint.h>

// Problem constants
#define BB   4
#define SS   128
#define TT   128
#define DD   256
#define NHEAD 8
#define HDIM  32
#define DFF  1024
#define NTOK (BB*SS*TT)          // 65536
#define EPSV 1.1920929e-07f
#define QK_SCALE_L2E (0.17677669529663687f * 1.44269504088896340f)

// ---------------- scratch ---------------------------------------------------
__device__ __half g_xh   [(size_t)NTOK * DD];
__device__ __half g_qkvh [(size_t)NTOK * 3 * DD];
__device__ __half g_attnh[(size_t)NTOK * DD];
__device__ __half g_hh   [(size_t)NTOK * DFF];
__device__ __half g_outh [(size_t)NTOK * DD];
__device__ __half g_wqs_h[3 * DD * DD];
__device__ __half g_wqt_h[3 * DD * DD];
__device__ __half g_wos_h[DD * DD];
__device__ __half g_wot_h[DD * DD];
__device__ __half g_w1_h [DFF * DD];
__device__ __half g_w2_h [DD * DFF];
__device__ float  g_ssq  [NTOK * 2];
__device__ uint32_t g_smaskbits[SS * 4];
__device__ uint32_t g_tmaskbits[TT * 4];

// ---------------- helpers ----------------------------------------------------
__device__ __forceinline__ uint32_t smem_u32(const void* p) {
    uint32_t a;
    asm("{ .reg .u64 t; cvta.to.shared.u64 t, %1; cvt.u32.u64 %0, t; }" : "=r"(a) : "l"(p));
    return a;
}
__device__ __forceinline__ void cp_async16(uint32_t dst, const void* src) {
    asm volatile("cp.async.cg.shared.global [%0], [%1], 16;" :: "r"(dst), "l"(src) : "memory");
}
__device__ __forceinline__ void cp_commit() {
    asm volatile("cp.async.commit_group;" ::: "memory");
}
template<int W> __device__ __forceinline__ void cp_wait() {
    asm volatile("cp.async.wait_group %0;" :: "n"(W) : "memory");
}
__device__ __forceinline__ void mma_f16(float* d, const uint32_t* a, const uint32_t* b) {
    asm volatile(
        "mma.sync.aligned.m16n8k16.row.col.f32.f16.f16.f32 "
        "{%0,%1,%2,%3}, {%4,%5,%6,%7}, {%8,%9}, {%0,%1,%2,%3};"
        : "+f"(d[0]), "+f"(d[1]), "+f"(d[2]), "+f"(d[3])
        : "r"(a[0]), "r"(a[1]), "r"(a[2]), "r"(a[3]), "r"(b[0]), "r"(b[1]));
}
__device__ __forceinline__ void ldsm_x4(uint32_t* r, uint32_t addr) {
    asm volatile("ldmatrix.sync.aligned.m8n8.x4.shared.b16 {%0,%1,%2,%3}, [%4];"
        : "=r"(r[0]), "=r"(r[1]), "=r"(r[2]), "=r"(r[3]) : "r"(addr));
}
__device__ __forceinline__ void ldsm_x4_t(uint32_t* r, uint32_t addr) {
    asm volatile("ldmatrix.sync.aligned.m8n8.x4.trans.shared.b16 {%0,%1,%2,%3}, [%4];"
        : "=r"(r[0]), "=r"(r[1]), "=r"(r[2]), "=r"(r[3]) : "r"(addr));
}
__device__ __forceinline__ uint32_t h2u(__half2 v) { return *(uint32_t*)&v; }
__device__ __forceinline__ uint32_t ex2_h2(uint32_t v) {
    uint32_t r;
    asm("ex2.approx.f16x2 %0, %1;" : "=r"(r) : "r"(v));
    return r;
}

// ---------------- fused prep: weights + masks (spatial+temporal) + rstd -------
#define PREP_BLKS  1028
#define RSTD_BLKS  (NTOK / 8)
__global__ void prep_k(const float* __restrict__ Wqkv_s, const float* __restrict__ g1,
                       const float* __restrict__ Wqkv_t, const float* __restrict__ g2,
                       const float* __restrict__ Wo_s, const float* __restrict__ Wo_t,
                       const float* __restrict__ W1, const float* __restrict__ g3,
                       const float* __restrict__ W2, const int* __restrict__ coords,
                       const float* __restrict__ x, __half* __restrict__ xh) {
    if (blockIdx.x >= PREP_BLKS) {
        int row  = (blockIdx.x - PREP_BLKS) * 8 + (threadIdx.x >> 5);
        int lane = threadIdx.x & 31;
        const float* xr = x + (size_t)row * DD + lane * 8;
        float4 a = *(const float4*)(xr);
        float4 b = *(const float4*)(xr + 4);
        float ss = a.x*a.x + a.y*a.y + a.z*a.z + a.w*a.w
                 + b.x*b.x + b.y*b.y + b.z*b.z + b.w*b.w;
        __half2 hh[4] = { __floats2half2_rn(a.x, a.y), __floats2half2_rn(a.z, a.w),
                          __floats2half2_rn(b.x, b.y), __floats2half2_rn(b.z, b.w) };
        *(uint4*)(xh + (size_t)row * DD + lane * 8) = *(uint4*)hh;
        #pragma unroll
        for (int m = 16; m > 0; m >>= 1) ss += __shfl_xor_sync(0xffffffffu, ss, m);
        if (lane == 0) { g_ssq[row * 2] = ss; g_ssq[row * 2 + 1] = 0.0f; }
        return;
    }
    int idx = blockIdx.x * 256 + threadIdx.x;
    if (idx < 262144) {
        const float* W; const float* g = nullptr; __half* out; int local;
        if (idx < 49152)       { W = Wqkv_s; g = g1; out = g_wqs_h; local = idx; }
        else if (idx < 98304)  { W = Wqkv_t; g = g2; out = g_wqt_h; local = idx - 49152; }
        else if (idx < 114688) { W = Wo_s;           out = g_wos_h; local = idx - 98304; }
        else if (idx < 131072) { W = Wo_t;           out = g_wot_h; local = idx - 114688; }
        else if (idx < 196608) { W = W1;     g = g3; out = g_w1_h;  local = idx - 131072; }
        else                   { W = W2;             out = g_w2_h;  local = idx - 196608; }
        float4 w = ((const float4*)W)[local];
        if (g) {
            float4 gv = ((const float4*)g)[local & (DD / 4 - 1)];
            w.x *= gv.x; w.y *= gv.y; w.z *= gv.z; w.w *= gv.w;
        }
        ((__half2*)out)[local * 2]     = __floats2half2_rn(w.x, w.y);
        ((__half2*)out)[local * 2 + 1] = __floats2half2_rn(w.z, w.w);
    } else if (idx < 262144 + 512) {
        int m = idx - 262144;
        int i = m >> 2, w = m & 3;
        uint32_t bits = 0;
        int xi = coords[2 * i], yi = coords[2 * i + 1];
        for (int k = 0; k < 32; k++) {
            int j = w * 32 + k;
            int dx = abs(xi - coords[2 * j]);
            int dy = abs(yi - coords[2 * j + 1]);
            if (max(dx, dy) <= 4) bits |= (1u << k);
        }
        g_smaskbits[m] = bits;
    } else if (idx < 262144 + 1024) {
        int m = idx - 262144 - 512;
        int i = m >> 2, w = m & 3;
        uint32_t bits = 0;
        for (int k = 0; k < 32; k++) {
            int j = w * 32 + k;
            int d = i - j;
            if (d >= 0 && d <= 3) bits |= (1u << k);
        }
        g_tmaskbits[m] = bits;
    }
}

// ---------------- fp16 mma GEMM (K compile-time) ------------------------------
#define HSTRIDE_B 144
#define ATILE_B   (128 * HSTRIDE_B)
#define STAGE_B   (2 * ATILE_B)
#define NSTAGE    3
#define GEMM_SMEM_BYTES (NSTAGE * STAGE_B)  // 110592
#define RES_ROW_B 528                        // residual smem row stride (fp32 + pad)

template<int EPI, bool NORM, bool WF32, bool WF16, bool SSQP, int KDIM>
__global__ void __launch_bounds__(256, 2) gemm_h_k(
    const __half* __restrict__ A, const __half* __restrict__ Bm,
    const float* __restrict__ bias, const float* __restrict__ res,
    float* __restrict__ Cf, __half* __restrict__ Ch, int M, int N)
{
    extern __shared__ char sm[];
    const int tid  = threadIdx.x;
    const int wid  = tid >> 5;
    const int lane = tid & 31;
    const int gid  = lane >> 2;
    const int tig  = lane & 3;
    const int warp_m = (wid & 1) * 64;
    const int warp_n = (wid >> 1) * 32;
    const int bm = blockIdx.y * 128;
    const int bn = blockIdx.x * 128;

    const uint32_t smbase = smem_u32(sm);

    uint32_t offA[4], offB[2];
    {
        const int aRow = lane & 15;
        const int aColB = (lane >> 4) * 16;
        #pragma unroll
        for (int mi = 0; mi < 4; mi++)
            offA[mi] = (uint32_t)(warp_m + mi * 16 + aRow) * HSTRIDE_B + aColB;
        const int bRow = (lane & 7) + (lane >> 4) * 8;
        const int bColB = (lane & 8) * 2;
        #pragma unroll
        for (int np = 0; np < 2; np++)
            offB[np] = (uint32_t)(warp_n + np * 16 + bRow) * HSTRIDE_B + bColB;
    }

    float acc[4][4][4];
    #pragma unroll
    for (int mi = 0; mi < 4; mi++)
        #pragma unroll
        for (int ni = 0; ni < 4; ni++)
            #pragma unroll
            for (int r = 0; r < 4; r++) acc[mi][ni][r] = 0.0f;

    constexpr int nCh = KDIM >> 6;
    const int ksRev = wid & 1;

    auto prefetch = [&](int ch, int s) {
        const int k0 = ch * 64;
        const uint32_t sa = smbase + (uint32_t)(s * STAGE_B);
        #pragma unroll
        for (int it = 0; it < 4; it++) {
            int f   = it * 256 + tid;
            int row = f >> 3;
            int c16 = f & 7;
            uint32_t off = (uint32_t)row * HSTRIDE_B + c16 * 16;
            cp_async16(sa + off,           A  + (size_t)(bm + row) * KDIM + k0 + c16 * 8);
            cp_async16(sa + off + ATILE_B, Bm + (size_t)(bn + row) * KDIM + k0 + c16 * 8);
        }
        cp_commit();
    };

    // stage 64 rows of the fp32 residual tile into smem (area after stage 0)
    auto stage_res = [&](int part) {
        const uint32_t rbase = smbase + (uint32_t)STAGE_B;
        #pragma unroll
        for (int it = 0; it < 8; it++) {
            int f   = it * 256 + tid;      // 0..2047 (16B units per part)
            int r   = f >> 5;              // 0..63
            int c16 = f & 31;              // 0..31 (128 floats / 4)
            cp_async16(rbase + (uint32_t)(part * 64 + r) * RES_ROW_B + c16 * 16,
                       res + (size_t)(bm + part * 64 + r) * N + bn + c16 * 4);
        }
        cp_commit();
    };

    prefetch(0, 0);
    if (nCh > 1) prefetch(1, 1);

    int stage = 0;
    #pragma unroll 4
    for (int ch = 0; ch < nCh; ch++) {
        cp_wait<1>();
        __syncthreads();

        if (ch + 2 < nCh) {
            int s2 = stage + 2; if (s2 >= NSTAGE) s2 -= NSTAGE;
            prefetch(ch + 2, s2);
        } else if (EPI == 1) {
            stage_res(ch - (nCh - 2));     // parts 0,1 in the last two chunks
        } else {
            cp_commit();
        }

        const uint32_t AsAddr = smbase + (uint32_t)(stage * STAGE_B);
        const uint32_t BsAddr = AsAddr + ATILE_B;

        #pragma unroll
        for (int ks = 0; ks < 4; ks++) {
            const int kss = ksRev ? (3 - ks) : ks;
            const uint32_t kb = (uint32_t)kss * 32;
            uint32_t a[4][4], b[2][4];
            #pragma unroll
            for (int mi = 0; mi < 4; mi++) ldsm_x4(a[mi], AsAddr + offA[mi] + kb);
            #pragma unroll
            for (int np = 0; np < 2; np++) ldsm_x4(b[np], BsAddr + offB[np] + kb);
            #pragma unroll
            for (int mi = 0; mi < 4; mi++)
                #pragma unroll
                for (int ni = 0; ni < 4; ni++)
                    mma_f16(acc[mi][ni], a[mi], &b[ni >> 1][(ni & 1) * 2]);
        }

        if (++stage == NSTAGE) stage = 0;
    }

    float* sred = (float*)sm;
    if (EPI == 1) { cp_wait<0>(); __syncthreads(); }
    else if (SSQP) __syncthreads();

    #pragma unroll
    for (int mi = 0; mi < 4; mi++) {
        #pragma unroll
        for (int h = 0; h < 2; h++) {
            const int rin = warp_m + mi * 16 + gid + h * 8;
            const int row = bm + rin;
            float rs = 1.0f;
            if (NORM) {
                float s2 = g_ssq[row * 2] + g_ssq[row * 2 + 1];
                rs = rsqrtf(s2 * (1.0f / DD) + EPSV);
            }
            float*  cf  = WF32 ? (Cf + (size_t)row * N) : (float*)nullptr;
            __half* chp = WF16 ? (Ch + (size_t)row * N) : (__half*)nullptr;
            const char* rrow = (EPI == 1) ? (sm + STAGE_B + (size_t)rin * RES_ROW_B) : (const char*)nullptr;
            float sp = 0.0f;
            #pragma unroll
            for (int ni = 0; ni < 4; ni++) {
                const int col = bn + warp_n + ni * 8 + tig * 2;
                const int cl  = warp_n + ni * 8 + tig * 2;   // tile-local col
                float v0 = acc[mi][ni][h * 2 + 0];
                float v1 = acc[mi][ni][h * 2 + 1];
                if (NORM) { v0 *= rs; v1 *= rs; }
                v0 += bias[col]; v1 += bias[col + 1];
                if (EPI == 1) {
                    float2 r = *(const float2*)(rrow + cl * 4);
                    v0 += r.x; v1 += r.y;
                }
                if (EPI == 2) {
                    v0 = 0.5f * v0 * (1.0f + erff(v0 * 0.70710678118654752f));
                    v1 = 0.5f * v1 * (1.0f + erff(v1 * 0.70710678118654752f));
                }
                if (SSQP) sp += v0 * v0 + v1 * v1;
                if (WF32) *(float2*)(cf + col) = make_float2(v0, v1);
                if (WF16) *(__half2*)(chp + col) = __floats2half2_rn(v0, v1);
            }
            if (SSQP) {
                sp += __shfl_xor_sync(0xffffffffu, sp, 1);
                sp += __shfl_xor_sync(0xffffffffu, sp, 2);
                if (tig == 0) sred[rin * 4 + (wid >> 1)] = sp;
            }
        }
    }

    if (SSQP) {
        __syncthreads();
        if (tid < 128) {
            float s = sred[tid * 4] + sred[tid * 4 + 1] + sred[tid * 4 + 2] + sred[tid * 4 + 3];
            g_ssq[(bm + tid) * 2 + blockIdx.x] = s;
        }
    }
}

// ---------------- fp16 MMA flash attention: 2 heads per block -----------------
#define AKS_HSTR (128 * 40)
#define AVS_HSTR (128 * 56)
#define AVS_H    (2 * AKS_HSTR)
#define AMB_BYTE ((AVS_H + 2 * AVS_HSTR) * 2)   // 49152
#define ASMEM_BYTES (AMB_BYTE + 2048)           // 51200

template<bool TEMPORAL>
__global__ void __launch_bounds__(256, 2) attn_mma_k(const __half* __restrict__ qkv,
                                                     __half* __restrict__ out)
{
    extern __shared__ __half ash[];
    uint32_t* MB = (uint32_t*)((char*)ash + AMB_BYTE);

    const int sb  = blockIdx.x;
    const int hbase = blockIdx.y * 2;
    const int tid = threadIdx.x;
    const int w   = tid >> 5;
    const int hp  = w >> 2;
    const int wg  = w & 3;
    const int lane = tid & 31;
    const int gid  = lane >> 2;
    const int tig  = lane & 3;

    const uint32_t KsAddr = smem_u32(ash) + hp * (AKS_HSTR * 2);
    const uint32_t VsAddr = smem_u32(ash) + AVS_H * 2 + hp * (AVS_HSTR * 2);
    const uint32_t KsStage = smem_u32(ash);
    const uint32_t VsStage = smem_u32(ash) + AVS_H * 2;

    const int bhi = sb >> 7, blo = sb & 127;

    #pragma unroll
    for (int it = 0; it < 4; it++) {
        int s    = it * 256 + tid;
        int tok  = s >> 3;
        int c16  = s & 7;
        int head = c16 >> 2;
        int q4   = c16 & 3;
        int tok_g = TEMPORAL ? (bhi * (TT * SS) + tok * SS + blo) : (sb * 128 + tok);
        const __half* base = qkv + (size_t)tok_g * (3 * DD) + (hbase + head) * HDIM + q4 * 8;
        cp_async16(KsStage + head * (AKS_HSTR * 2) + tok * 80  + q4 * 16, base + DD);
        cp_async16(VsStage + head * (AVS_HSTR * 2) + tok * 112 + q4 * 16, base + 2 * DD);
    }
    cp_commit();

    {
        int head = tid >> 7, tok = tid & 127;
        __half* vp = ash + AVS_H + head * AVS_HSTR + tok * 56 + 32;
        uint4 z  = make_uint4(0, 0, 0, 0);
        uint4 o1 = make_uint4(0x00003C00u, 0, 0, 0);
        *(uint4*)(vp)      = o1;
        *(uint4*)(vp + 8)  = z;
        *(uint4*)(vp + 16) = z;
    }
    {
        const uint32_t* gmb = TEMPORAL ? g_tmaskbits : g_smaskbits;
        for (int i = tid; i < 512; i += 256) MB[i] = gmb[i];
    }

    const int h = hbase + hp;
    const int qbase = wg * 32;
    const __half2 qs2 = __float2half2_rn(QK_SCALE_L2E);

    uint32_t qa[2][2][4];
    #pragma unroll
    for (int mt = 0; mt < 2; mt++) {
        int rA = qbase + mt * 16 + gid;
        int tokA = TEMPORAL ? (bhi * (TT * SS) + rA * SS + blo) : (sb * 128 + rA);
        int tokB = TEMPORAL ? (bhi * (TT * SS) + (rA + 8) * SS + blo) : (sb * 128 + rA + 8);
        const __half* pA = qkv + (size_t)tokA * (3 * DD) + h * HDIM;
        const __half* pB = qkv + (size_t)tokB * (3 * DD) + h * HDIM;
        #pragma unroll
        for (int ks = 0; ks < 2; ks++) {
            qa[mt][ks][0] = h2u(__hmul2(*(const __half2*)(pA + ks * 16 + 2 * tig), qs2));
            qa[mt][ks][1] = h2u(__hmul2(*(const __half2*)(pB + ks * 16 + 2 * tig), qs2));
            qa[mt][ks][2] = h2u(__hmul2(*(const __half2*)(pA + ks * 16 + 2 * tig + 8), qs2));
            qa[mt][ks][3] = h2u(__hmul2(*(const __half2*)(pB + ks * 16 + 2 * tig + 8), qs2));
        }
    }

    cp_wait<0>();
    __syncthreads();

    const int bRow  = (lane & 7) + (lane >> 4) * 8;
    const int bColB = (lane & 8) * 2;
    const int vRow  = (lane & 7) + ((lane >> 3) & 1) * 8;
    const int vColH = ((lane >> 4) & 1) * 8;

    float o[2][4][4];
    float oS[2][4];
    #pragma unroll
    for (int mt = 0; mt < 2; mt++) {
        #pragma unroll
        for (int r = 0; r < 4; r++) oS[mt][r] = 0.0f;
        #pragma unroll
        for (int nt = 0; nt < 4; nt++)
            #pragma unroll
            for (int r = 0; r < 4; r++) o[mt][nt][r] = 0.0f;
    }

    const int jc_lo = TEMPORAL ? max(wg - 1, 0) : 0;
    const int jc_hi = TEMPORAL ? wg : 3;

    for (int jc = jc_lo; jc <= jc_hi; jc++) {
        float s[2][4][4];
        #pragma unroll
        for (int mt = 0; mt < 2; mt++)
            #pragma unroll
            for (int nt = 0; nt < 4; nt++)
                #pragma unroll
                for (int r = 0; r < 4; r++) s[mt][nt][r] = 0.0f;

        #pragma unroll
        for (int ks = 0; ks < 2; ks++) {
            uint32_t bk[2][4];
            #pragma unroll
            for (int np = 0; np < 2; np++) {
                uint32_t addr = KsAddr + (uint32_t)(jc * 32 + np * 16 + bRow) * 80
                              + bColB + ks * 32;
                ldsm_x4(bk[np], addr);
            }
            #pragma unroll
            for (int mt = 0; mt < 2; mt++)
                #pragma unroll
                for (int nt = 0; nt < 4; nt++)
                    mma_f16(s[mt][nt], qa[mt][ks], &bk[nt >> 1][(nt & 1) * 2]);
        }

        uint32_t ph[2][4][2];
        #pragma unroll
        for (int mt = 0; mt < 2; mt++) {
            int row0 = qbase + mt * 16 + gid;
            uint32_t mw0 = MB[row0 * 4 + jc];
            uint32_t mw1 = MB[(row0 + 8) * 4 + jc];
            #pragma unroll
            for (int nt = 0; nt < 4; nt++) {
                float sm0[2], sm1[2];
                #pragma unroll
                for (int c = 0; c < 2; c++) {
                    int kloc = nt * 8 + 2 * tig + c;
                    bool v0 = (mw0 >> kloc) & 1;
                    bool v1 = (mw1 >> kloc) & 1;
                    sm0[c] = v0 ? s[mt][nt][c]     : -50.0f;
                    sm1[c] = v1 ? s[mt][nt][c + 2] : -50.0f;
                }
                ph[mt][nt][0] = ex2_h2(h2u(__floats2half2_rn(sm0[0], sm0[1])));
                ph[mt][nt][1] = ex2_h2(h2u(__floats2half2_rn(sm1[0], sm1[1])));
            }
        }

        #pragma unroll
        for (int ks = 0; ks < 2; ks++) {
            uint32_t bv[3][4];
            #pragma unroll
            for (int np = 0; np < 3; np++) {
                uint32_t addr = VsAddr + (uint32_t)(jc * 32 + ks * 16 + vRow) * 112
                              + (np * 16 + vColH) * 2;
                ldsm_x4_t(bv[np], addr);
            }
            #pragma unroll
            for (int mt = 0; mt < 2; mt++) {
                uint32_t a[4] = { ph[mt][2 * ks][0],     ph[mt][2 * ks][1],
                                  ph[mt][2 * ks + 1][0], ph[mt][2 * ks + 1][1] };
                #pragma unroll
                for (int nt = 0; nt < 4; nt++)
                    mma_f16(o[mt][nt], a, &bv[nt >> 1][(nt & 1) * 2]);
                mma_f16(oS[mt], a, &bv[2][0]);
            }
        }
    }

    #pragma unroll
    for (int mt = 0; mt < 2; mt++) {
        #pragma unroll
        for (int h2 = 0; h2 < 2; h2++) {
            float l = __shfl_sync(0xffffffffu, oS[mt][h2 * 2], lane & ~3);
            float inv = 1.0f / l;
            int grow = qbase + mt * 16 + gid + h2 * 8;
            int tok  = TEMPORAL ? (bhi * (TT * SS) + grow * SS + blo) : (sb * 128 + grow);
            __half* op = out + (size_t)tok * DD + h * HDIM;
            #pragma unroll
            for (int nt = 0; nt < 4; nt++) {
                *(__half2*)(op + nt * 8 + 2 * tig) =
                    __floats2half2_rn(o[mt][nt][2 * h2] * inv, o[mt][nt][2 * h2 + 1] * inv);
            }
        }
    }
}

// ---------------- launch -----------------------------------------------------
extern "C" void kernel_launch(void* const* d_in, const int* in_sizes, int n_in,
                              void* d_out, int out_size) {
    const float* x      = (const float*)d_in[0];
    const int*   coords = (const int*)  d_in[1];
    const float* Wqkv_s = (const float*)d_in[3];
    const float* bqkv_s = (const float*)d_in[4];
    const float* Wo_s   = (const float*)d_in[5];
    const float* bo_s   = (const float*)d_in[6];
    const float* Wqkv_t = (const float*)d_in[7];
    const float* bqkv_t = (const float*)d_in[8];
    const float* Wo_t   = (const float*)d_in[9];
    const float* bo_t   = (const float*)d_in[10];
    const float* g1     = (const float*)d_in[11];
    const float* g2     = (const float*)d_in[12];
    const float* g3     = (const float*)d_in[13];
    const float* W1     = (const float*)d_in[14];
    const float* b1     = (const float*)d_in[15];
    const float* W2     = (const float*)d_in[16];
    const float* b2     = (const float*)d_in[17];
    float* out = (float*)d_out;

    __half *xh, *qkvh, *attnh, *hh, *outh, *wqs, *wqt, *wos, *wot, *w1h, *w2h;
    cudaGetSymbolAddress((void**)&xh,    g_xh);
    cudaGetSymbolAddress((void**)&qkvh,  g_qkvh);
    cudaGetSymbolAddress((void**)&attnh, g_attnh);
    cudaGetSymbolAddress((void**)&hh,    g_hh);
    cudaGetSymbolAddress((void**)&outh,  g_outh);
    cudaGetSymbolAddress((void**)&wqs,   g_wqs_h);
    cudaGetSymbolAddress((void**)&wqt,   g_wqt_h);
    cudaGetSymbolAddress((void**)&wos,   g_wos_h);
    cudaGetSymbolAddress((void**)&wot,   g_wot_h);
    cudaGetSymbolAddress((void**)&w1h,   g_w1_h);
    cudaGetSymbolAddress((void**)&w2h,   g_w2_h);

    static bool attr_set = false;
    if (!attr_set) {
        cudaFuncSetAttribute(gemm_h_k<0,true,false,true,false,256>, cudaFuncAttributeMaxDynamicSharedMemorySize, GEMM_SMEM_BYTES);
        cudaFuncSetAttribute(gemm_h_k<1,false,true,true,true,256>,  cudaFuncAttributeMaxDynamicSharedMemorySize, GEMM_SMEM_BYTES);
        cudaFuncSetAttribute(gemm_h_k<2,true,false,true,false,256>, cudaFuncAttributeMaxDynamicSharedMemorySize, GEMM_SMEM_BYTES);
        cudaFuncSetAttribute(gemm_h_k<1,false,true,false,false,1024>,cudaFuncAttributeMaxDynamicSharedMemorySize, GEMM_SMEM_BYTES);
        cudaFuncSetAttribute(attn_mma_k<false>, cudaFuncAttributeMaxDynamicSharedMemorySize, ASMEM_BYTES);
        cudaFuncSetAttribute(attn_mma_k<true>,  cudaFuncAttributeMaxDynamicSharedMemorySize, ASMEM_BYTES);
        attr_set = true;
    }

    const dim3 tb256(256);
    const dim3 gQKV(3 * DD / 128, NTOK / 128);   // (6, 512)
    const dim3 gO  (DD / 128,     NTOK / 128);   // (2, 512)
    const dim3 gF1 (DFF / 128,    NTOK / 128);   // (8, 512)
    const dim3 gAttn(BB * TT, NHEAD / 2);        // (512, 4)

    prep_k<<<PREP_BLKS + RSTD_BLKS, tb256>>>(Wqkv_s, g1, Wqkv_t, g2, Wo_s, Wo_t, W1, g3, W2,
                                             coords, x, xh);

    // --- spatial block ---
    gemm_h_k<0,true,false,true,false,256><<<gQKV, tb256, GEMM_SMEM_BYTES>>>(
        xh, wqs, bqkv_s, nullptr, nullptr, qkvh, NTOK, 3 * DD);
    attn_mma_k<false><<<gAttn, tb256, ASMEM_BYTES>>>(qkvh, attnh);
    gemm_h_k<1,false,true,true,true,256><<<gO, tb256, GEMM_SMEM_BYTES>>>(
        attnh, wos, bo_s, x, out, outh, NTOK, DD);

    // --- temporal block ---
    gemm_h_k<0,true,false,true,false,256><<<gQKV, tb256, GEMM_SMEM_BYTES>>>(
        outh, wqt, bqkv_t, nullptr, nullptr, qkvh, NTOK, 3 * DD);
    attn_mma_k<true><<<gAttn, tb256, ASMEM_BYTES>>>(qkvh, attnh);
    gemm_h_k<1,false,true,true,true,256><<<gO, tb256, GEMM_SMEM_BYTES>>>(
        attnh, wot, bo_t, out, out, outh, NTOK, DD);

    // --- FFN ---
    gemm_h_k<2,true,false,true,false,256><<<gF1, tb256, GEMM_SMEM_BYTES>>>(
        outh, w1h, b1, nullptr, nullptr, hh, NTOK, DFF);
    gemm_h_k<1,false,true,false,false,1024><<<gO, tb256, GEMM_SMEM_BYTES>>>(
        hh, w2h, b2, out, out, nullptr, NTOK, DD);
}